// round 13
// baseline (speedup 1.0000x reference)
#include <cuda_runtime.h>
#include <cuda_fp16.h>
#include <cstdint>

// ================= problem constants =================
#define NROWS 4096
#define EMB   768
#define NC    97
#define KTOT  49152          // 768 * 64
#define NTILES 13            // 13 x n8 = 104 >= 97
#define SPLITS 9             // 144 CTAs total (16 x 9)
#define THREADS 256
#define M_PER_CTA 256        // 8 warps x 32 rows

// W smem layout: per class row 160B stride; k16-step ks at byte ks*32,
// fragment pair lr at +lr*8 = [b0|b1]. ld.shared.v2.b32 conflict-free.
#define W_ROW_STRIDE 160
#define WSTAGE (104 * W_ROW_STRIDE)     // 16640 B per K64 chunk
#define QUAD   4                        // chunks per pipeline stage (K256)
#define SMEM_BYTES (2 * QUAD * WSTAGE)  // 2-slot ring = 133120 B

__device__ __align__(16) uint32_t g_Wh[NC * KTOT / 2];           // ~9.5 MB

__device__ __forceinline__ uint32_t f22h(float a, float b) {
    __half2 h = __floats2half2_rn(a, b);
    return *reinterpret_cast<uint32_t*>(&h);
}
__device__ __forceinline__ uint32_t hmul2u(uint32_t a, uint32_t s) {
    __half2 r = __hmul2(*reinterpret_cast<__half2*>(&a), *reinterpret_cast<__half2*>(&s));
    return *reinterpret_cast<uint32_t*>(&r);
}
__device__ __forceinline__ uint32_t smem_u32(const void* p) {
    uint32_t a;
    asm("{ .reg .u64 t; cvta.to.shared.u64 t, %1; cvt.u32.u64 %0, t; }" : "=r"(a) : "l"(p));
    return a;
}
__device__ __forceinline__ void cp16(uint32_t dst, const void* src) {
    asm volatile("cp.async.cg.shared.global [%0], [%1], 16;" :: "r"(dst), "l"(src));
}
#define CP_COMMIT()   asm volatile("cp.async.commit_group;" ::: "memory")
#define CP_WAIT_ALL() asm volatile("cp.async.wait_group 0;" ::: "memory")
__device__ __forceinline__ void redg_add(float* p, float v) {
    asm volatile("red.global.add.f32 [%0], %1;" :: "l"(p), "f"(v) : "memory");
}

// m16n8k16 fp16->fp32 mma, D==C in-place accumulate (baseline PTX, sm_80+)
#define MMA16816(d, a0, a1, a2, a3, b0, b1)                                      \
    asm volatile("mma.sync.aligned.m16n8k16.row.col.f32.f16.f16.f32 "            \
        "{%0,%1,%2,%3},{%4,%5,%6,%7},{%8,%9},{%0,%1,%2,%3};\n"                   \
        : "+f"((d)[0]), "+f"((d)[1]), "+f"((d)[2]), "+f"((d)[3])                 \
        : "r"(a0), "r"(a1), "r"(a2), "r"(a3), "r"(b0), "r"(b1))

// ================= kernels =================
// W fp32 -> fp16, remapped so each k16 fragment pair lies contiguous.
__global__ void convert_w(const float4* __restrict__ W4) {
    size_t idx = (size_t)blockIdx.x * 256 + threadIdx.x;
    if (idx >= (size_t)NC * KTOT / 4) return;
    size_t j4 = idx * 4;
    int    ce = (int)(j4 & 63);
    int    ks = ce >> 4, h = (ce >> 3) & 1, q = (ce >> 2) & 1;
    size_t base_u32 = (j4 - ce) >> 1;
    int    w0 = ks * 8 + q * 4 + h;
    float4 v = W4[idx];
    g_Wh[base_u32 + w0]     = f22h(v.x, v.y);
    g_Wh[base_u32 + w0 + 2] = f22h(v.z, v.w);
}

__global__ void init_bias(const float* __restrict__ b, float* __restrict__ out) {
    int idx = blockIdx.x * 256 + threadIdx.x;
    if (idx < NROWS * NC) out[idx] = b[idx % NC];
}

// stage a K256 quad (4 chunks) of W into the smem ring (async)
__device__ __forceinline__ void stage_quad(uint32_t dst, int chunk, int t) {
#pragma unroll
    for (int c2 = 0; c2 < QUAD; ++c2) {
        const char* src = (const char*)g_Wh + (size_t)(chunk + c2) * 128;
#pragma unroll
        for (int base = 0; base < NC * 8; base += THREADS) {
            int idx = base + t;
            if (idx < NC * 8) {
                int c = idx >> 3, g = idx & 7;
                cp16(dst + c2 * WSTAGE + c * W_ROW_STRIDE + g * 16,
                     src + (size_t)c * (KTOT * 2) + g * 16);
            }
        }
    }
    CP_COMMIT();
}

__global__ void __launch_bounds__(THREADS, 1) bilinear_mma(
    const float* __restrict__ head, const float* __restrict__ tail,
    float* __restrict__ out)
{
    extern __shared__ __align__(16) char ws[];
    const uint32_t ws_u32 = smem_u32(ws);

    const int t     = threadIdx.x;
    const int w     = t >> 5;
    const int lane  = t & 31;
    const int lq    = lane >> 2;
    const int lr    = lane & 3;
    const int mbase = blockIdx.x * M_PER_CTA;
    const int split = blockIdx.y;
    // 192 K256-quads over 9 splits: 3 splits of 22, 6 of 21
    const int quad0  = split * 21 + (split < 3 ? split : 3);
    const int nq     = 21 + (split < 3 ? 1 : 0);
    const int chunk0 = quad0 * QUAD;
    const int R      = mbase + 32 * w;

    // zero both ring slots once (pad classes 97..103 stay 0 forever)
    for (int i = t; i < SMEM_BYTES / 4; i += THREADS)
        reinterpret_cast<uint32_t*>(ws)[i] = 0;
    __syncthreads();

    // master accumulators: [mtile][ntile][4] = 32 rows x 104 cols per warp
    float acc[2][NTILES][4];
#pragma unroll
    for (int mt = 0; mt < 2; ++mt)
#pragma unroll
        for (int nt = 0; nt < NTILES; ++nt)
#pragma unroll
            for (int q = 0; q < 4; ++q) acc[mt][nt][q] = 0.0f;

    // unscaled fp16 b2 fragments, static per k-block: [mtile][kstep][4]
    uint32_t bse[2][4][4];
    int curk = -1;

    stage_quad(ws_u32, chunk0, t);

#pragma unroll 1
    for (int qi = 0; qi < nq; ++qi) {
        const int chunk = chunk0 + QUAD * qi;
        const int kblk  = chunk >> 6;        // constant across the quad
        const int slot  = qi & 1;

        CP_WAIT_ALL();
        __syncthreads();   // quad(qi) ready; other ring slot consumers done

        if (qi + 1 < nq)
            stage_quad(ws_u32 + (1 - slot) * QUAD * WSTAGE, chunk + QUAD, t);

        // ---- refill b2 base fragments on k-block change ----
        if (kblk != curk) {
            curk = kblk;
#pragma unroll
            for (int mt = 0; mt < 2; ++mt) {
                const float* p0 = tail + (size_t)(R + 16 * mt + lq) * EMB + kblk * 64 + lr * 2;
                const float* p1 = p0 + 8 * EMB;
#pragma unroll
                for (int ks = 0; ks < 4; ++ks) {
                    float2 v0 = *reinterpret_cast<const float2*>(p0 + ks * 16);
                    float2 v1 = *reinterpret_cast<const float2*>(p1 + ks * 16);
                    float2 v2 = *reinterpret_cast<const float2*>(p0 + ks * 16 + 8);
                    float2 v3 = *reinterpret_cast<const float2*>(p1 + ks * 16 + 8);
                    bse[mt][ks][0] = f22h(v0.x, v0.y);
                    bse[mt][ks][1] = f22h(v1.x, v1.y);
                    bse[mt][ks][2] = f22h(v2.x, v2.y);
                    bse[mt][ks][3] = f22h(v3.x, v3.y);
                }
            }
        }

        // ---- batch-prefetch b1 scalars for all 4 sub-chunks (1 LDG.128/row) ----
        const size_t hcol0 = (size_t)kblk * 64 + (chunk & 63);
        float4 f0a = *reinterpret_cast<const float4*>(head + (size_t)(R +  0 + lq) * EMB + hcol0);
        float4 f0b = *reinterpret_cast<const float4*>(head + (size_t)(R +  8 + lq) * EMB + hcol0);
        float4 f1a = *reinterpret_cast<const float4*>(head + (size_t)(R + 16 + lq) * EMB + hcol0);
        float4 f1b = *reinterpret_cast<const float4*>(head + (size_t)(R + 24 + lq) * EMB + hcol0);
        const float s0a[4] = {f0a.x, f0a.y, f0a.z, f0a.w};
        const float s0b[4] = {f0b.x, f0b.y, f0b.z, f0b.w};
        const float s1a[4] = {f1a.x, f1a.y, f1a.z, f1a.w};
        const float s1b[4] = {f1b.x, f1b.y, f1b.z, f1b.w};

#pragma unroll
        for (int sub = 0; sub < QUAD; ++sub) {
            __half2 h0a = __float2half2_rn(s0a[sub]);
            __half2 h0b = __float2half2_rn(s0b[sub]);
            __half2 h1a = __float2half2_rn(s1a[sub]);
            __half2 h1b = __float2half2_rn(s1b[sub]);
            const uint32_t u0a = *reinterpret_cast<uint32_t*>(&h0a);
            const uint32_t u0b = *reinterpret_cast<uint32_t*>(&h0b);
            const uint32_t u1a = *reinterpret_cast<uint32_t*>(&h1a);
            const uint32_t u1b = *reinterpret_cast<uint32_t*>(&h1b);

            const uint32_t wb = ws_u32 + (slot * QUAD + sub) * WSTAGE
                              + lq * W_ROW_STRIDE + lr * 8;

            // ks-outer / nt-inner: dependent MMAs 26 apart -> pipe-rate bound
#pragma unroll
            for (int ks = 0; ks < 4; ++ks) {
                uint32_t a00 = hmul2u(bse[0][ks][0], u0a);
                uint32_t a01 = hmul2u(bse[0][ks][1], u0b);
                uint32_t a02 = hmul2u(bse[0][ks][2], u0a);
                uint32_t a03 = hmul2u(bse[0][ks][3], u0b);
                uint32_t a10 = hmul2u(bse[1][ks][0], u1a);
                uint32_t a11 = hmul2u(bse[1][ks][1], u1b);
                uint32_t a12 = hmul2u(bse[1][ks][2], u1a);
                uint32_t a13 = hmul2u(bse[1][ks][3], u1b);
#pragma unroll
                for (int nt = 0; nt < NTILES; ++nt) {
                    uint32_t b0, b1;
                    asm volatile("ld.shared.v2.b32 {%0,%1}, [%2];"
                        : "=r"(b0), "=r"(b1)
                        : "r"(wb + nt * (8 * W_ROW_STRIDE) + ks * 32));
                    MMA16816(acc[0][nt], a00, a01, a02, a03, b0, b1);
                    MMA16816(acc[1][nt], a10, a11, a12, a13, b0, b1);
                }
            }
        }
    }

    // ---- epilogue: fused split-K reduction via red.global.add ----
#pragma unroll
    for (int mt = 0; mt < 2; ++mt) {
        const int r0 = R + 16 * mt + lq;
#pragma unroll
        for (int nt = 0; nt < NTILES; ++nt) {
            const int col = nt * 8 + lr * 2;
            if (col < NC) {
                redg_add(out + (size_t)r0 * NC + col,       acc[mt][nt][0]);
                redg_add(out + (size_t)(r0 + 8) * NC + col, acc[mt][nt][2]);
            }
            if (col + 1 < NC) {
                redg_add(out + (size_t)r0 * NC + col + 1,       acc[mt][nt][1]);
                redg_add(out + (size_t)(r0 + 8) * NC + col + 1, acc[mt][nt][3]);
            }
        }
    }
}

// ================= launch =================
extern "C" void kernel_launch(void* const* d_in, const int* in_sizes, int n_in,
                              void* d_out, int out_size) {
    const float* head = (const float*)d_in[0];
    const float* tail = (const float*)d_in[1];
    const float* W    = (const float*)d_in[2];
    const float* b    = (const float*)d_in[3];
    float* out        = (float*)d_out;

    cudaFuncSetAttribute(bilinear_mma,
                         cudaFuncAttributeMaxDynamicSharedMemorySize, SMEM_BYTES);

    // 1) W -> fp16, fragment-interleaved (L2-resident afterwards)
    convert_w<<<(NC * KTOT / 4 + 255) / 256, 256>>>((const float4*)W);
    // 2) out = bias broadcast (out is poisoned before timing)
    init_bias<<<(NROWS * NC + 255) / 256, 256>>>(b, out);
    // 3) fused bilinear GEMM, split-K accumulated into out via REDG
    dim3 grid(NROWS / M_PER_CTA, SPLITS);   // (16, 9) = 144 CTAs
    bilinear_mma<<<grid, THREADS, SMEM_BYTES>>>(head, tail, out);
}

// round 14
// speedup vs baseline: 1.0095x; 1.0095x over previous
#include <cuda_runtime.h>
#include <cuda_fp16.h>
#include <cstdint>

// ================= problem constants =================
#define NROWS 4096
#define EMB   768
#define NC    97
#define KTOT  49152          // 768 * 64
#define NTILES 13            // 13 x n8 = 104 >= 97
#define SPLITS 9             // 144 CTAs total (16 x 9)
#define THREADS 256
#define M_PER_CTA 256        // 8 warps x 32 rows

// W smem layout: per class row 160B stride; k16-step ks at byte ks*32,
// fragment pair lr at +lr*8 = [b0|b1]. ld.shared.v2.b32 conflict-free.
#define W_ROW_STRIDE 160
#define WSTAGE (104 * W_ROW_STRIDE)     // 16640 B per K64 chunk
#define QUAD   4                        // chunks per pipeline stage (K256)
#define SMEM_BYTES (2 * QUAD * WSTAGE)  // 2-slot ring = 133120 B

__device__ __align__(16) uint32_t g_Wh[NC * KTOT / 2];           // ~9.5 MB

__device__ __forceinline__ uint32_t f22h(float a, float b) {
    __half2 h = __floats2half2_rn(a, b);
    return *reinterpret_cast<uint32_t*>(&h);
}
__device__ __forceinline__ uint32_t hmul2u(uint32_t a, uint32_t s) {
    __half2 r = __hmul2(*reinterpret_cast<__half2*>(&a), *reinterpret_cast<__half2*>(&s));
    return *reinterpret_cast<uint32_t*>(&r);
}
__device__ __forceinline__ uint32_t smem_u32(const void* p) {
    uint32_t a;
    asm("{ .reg .u64 t; cvta.to.shared.u64 t, %1; cvt.u32.u64 %0, t; }" : "=r"(a) : "l"(p));
    return a;
}
__device__ __forceinline__ void cp16(uint32_t dst, const void* src) {
    asm volatile("cp.async.cg.shared.global [%0], [%1], 16;" :: "r"(dst), "l"(src));
}
#define CP_COMMIT()   asm volatile("cp.async.commit_group;" ::: "memory")
#define CP_WAIT_ALL() asm volatile("cp.async.wait_group 0;" ::: "memory")
__device__ __forceinline__ void redg_add(float* p, float v) {
    asm volatile("red.global.add.f32 [%0], %1;" :: "l"(p), "f"(v) : "memory");
}

// m16n8k16 fp16->fp32 mma, D==C in-place accumulate (baseline PTX, sm_80+)
#define MMA16816(d, a0, a1, a2, a3, b0, b1)                                      \
    asm volatile("mma.sync.aligned.m16n8k16.row.col.f32.f16.f16.f32 "            \
        "{%0,%1,%2,%3},{%4,%5,%6,%7},{%8,%9},{%0,%1,%2,%3};\n"                   \
        : "+f"((d)[0]), "+f"((d)[1]), "+f"((d)[2]), "+f"((d)[3])                 \
        : "r"(a0), "r"(a1), "r"(a2), "r"(a3), "r"(b0), "r"(b1))

// ================= kernels =================
// W fp32 -> fp16, remapped so each k16 fragment pair lies contiguous.
__global__ void convert_w(const float4* __restrict__ W4) {
    size_t idx = (size_t)blockIdx.x * 256 + threadIdx.x;
    if (idx >= (size_t)NC * KTOT / 4) return;
    size_t j4 = idx * 4;
    int    ce = (int)(j4 & 63);
    int    ks = ce >> 4, h = (ce >> 3) & 1, q = (ce >> 2) & 1;
    size_t base_u32 = (j4 - ce) >> 1;
    int    w0 = ks * 8 + q * 4 + h;
    float4 v = W4[idx];
    g_Wh[base_u32 + w0]     = f22h(v.x, v.y);
    g_Wh[base_u32 + w0 + 2] = f22h(v.z, v.w);
}

__global__ void init_bias(const float* __restrict__ b, float* __restrict__ out) {
    int idx = blockIdx.x * 256 + threadIdx.x;
    if (idx < NROWS * NC) out[idx] = b[idx % NC];
}

// stage a K256 quad (4 chunks) of W into the smem ring (async)
__device__ __forceinline__ void stage_quad(uint32_t dst, int chunk, int t) {
#pragma unroll
    for (int c2 = 0; c2 < QUAD; ++c2) {
        const char* src = (const char*)g_Wh + (size_t)(chunk + c2) * 128;
#pragma unroll
        for (int base = 0; base < NC * 8; base += THREADS) {
            int idx = base + t;
            if (idx < NC * 8) {
                int c = idx >> 3, g = idx & 7;
                cp16(dst + c2 * WSTAGE + c * W_ROW_STRIDE + g * 16,
                     src + (size_t)c * (KTOT * 2) + g * 16);
            }
        }
    }
    CP_COMMIT();
}

__global__ void __launch_bounds__(THREADS, 1) bilinear_mma(
    const float* __restrict__ head, const float* __restrict__ tail,
    float* __restrict__ out)
{
    extern __shared__ __align__(16) char ws[];
    const uint32_t ws_u32 = smem_u32(ws);

    const int t     = threadIdx.x;
    const int w     = t >> 5;
    const int lane  = t & 31;
    const int lq    = lane >> 2;
    const int lr    = lane & 3;
    const int mbase = blockIdx.x * M_PER_CTA;
    const int split = blockIdx.y;
    // 192 K256-quads over 9 splits: 3 splits of 22, 6 of 21
    const int quad0  = split * 21 + (split < 3 ? split : 3);
    const int nq     = 21 + (split < 3 ? 1 : 0);
    const int chunk0 = quad0 * QUAD;
    const int R      = mbase + 32 * w;

    // zero both ring slots once (pad classes 97..103 stay 0 forever)
    for (int i = t; i < SMEM_BYTES / 4; i += THREADS)
        reinterpret_cast<uint32_t*>(ws)[i] = 0;
    __syncthreads();

    // master accumulators: [mtile][ntile][4] = 32 rows x 104 cols per warp
    float acc[2][NTILES][4];
#pragma unroll
    for (int mt = 0; mt < 2; ++mt)
#pragma unroll
        for (int nt = 0; nt < NTILES; ++nt)
#pragma unroll
            for (int q = 0; q < 4; ++q) acc[mt][nt][q] = 0.0f;

    // unscaled fp16 b2 fragments, static per k-block: [mtile][kstep][4]
    uint32_t bse[2][4][4];
    int curk = -1;

    stage_quad(ws_u32, chunk0, t);

#pragma unroll 1
    for (int qi = 0; qi < nq; ++qi) {
        const int chunk = chunk0 + QUAD * qi;
        const int kblk  = chunk >> 6;        // constant across the quad
        const int slot  = qi & 1;

        CP_WAIT_ALL();
        __syncthreads();   // quad(qi) ready; other ring slot consumers done

        if (qi + 1 < nq)
            stage_quad(ws_u32 + (1 - slot) * QUAD * WSTAGE, chunk + QUAD, t);

        // ---- refill b2 base fragments on k-block change ----
        if (kblk != curk) {
            curk = kblk;
#pragma unroll
            for (int mt = 0; mt < 2; ++mt) {
                const float* p0 = tail + (size_t)(R + 16 * mt + lq) * EMB + kblk * 64 + lr * 2;
                const float* p1 = p0 + 8 * EMB;
#pragma unroll
                for (int ks = 0; ks < 4; ++ks) {
                    float2 v0 = *reinterpret_cast<const float2*>(p0 + ks * 16);
                    float2 v1 = *reinterpret_cast<const float2*>(p1 + ks * 16);
                    float2 v2 = *reinterpret_cast<const float2*>(p0 + ks * 16 + 8);
                    float2 v3 = *reinterpret_cast<const float2*>(p1 + ks * 16 + 8);
                    bse[mt][ks][0] = f22h(v0.x, v0.y);
                    bse[mt][ks][1] = f22h(v1.x, v1.y);
                    bse[mt][ks][2] = f22h(v2.x, v2.y);
                    bse[mt][ks][3] = f22h(v3.x, v3.y);
                }
            }
        }

        // ---- batch-prefetch b1 scalars for all 4 sub-chunks (1 LDG.128/row) ----
        const size_t hcol0 = (size_t)kblk * 64 + (chunk & 63);
        float4 f0a = *reinterpret_cast<const float4*>(head + (size_t)(R +  0 + lq) * EMB + hcol0);
        float4 f0b = *reinterpret_cast<const float4*>(head + (size_t)(R +  8 + lq) * EMB + hcol0);
        float4 f1a = *reinterpret_cast<const float4*>(head + (size_t)(R + 16 + lq) * EMB + hcol0);
        float4 f1b = *reinterpret_cast<const float4*>(head + (size_t)(R + 24 + lq) * EMB + hcol0);
        const float s0a[4] = {f0a.x, f0a.y, f0a.z, f0a.w};
        const float s0b[4] = {f0b.x, f0b.y, f0b.z, f0b.w};
        const float s1a[4] = {f1a.x, f1a.y, f1a.z, f1a.w};
        const float s1b[4] = {f1b.x, f1b.y, f1b.z, f1b.w};

#pragma unroll
        for (int sub = 0; sub < QUAD; ++sub) {
            __half2 h0a = __float2half2_rn(s0a[sub]);
            __half2 h0b = __float2half2_rn(s0b[sub]);
            __half2 h1a = __float2half2_rn(s1a[sub]);
            __half2 h1b = __float2half2_rn(s1b[sub]);
            const uint32_t u0a = *reinterpret_cast<uint32_t*>(&h0a);
            const uint32_t u0b = *reinterpret_cast<uint32_t*>(&h0b);
            const uint32_t u1a = *reinterpret_cast<uint32_t*>(&h1a);
            const uint32_t u1b = *reinterpret_cast<uint32_t*>(&h1b);

            const uint32_t wb = ws_u32 + (slot * QUAD + sub) * WSTAGE
                              + lq * W_ROW_STRIDE + lr * 8;

            // ks-outer / nt-inner: dependent MMAs 26 apart -> pipe-rate bound
#pragma unroll
            for (int ks = 0; ks < 4; ++ks) {
                uint32_t a00 = hmul2u(bse[0][ks][0], u0a);
                uint32_t a01 = hmul2u(bse[0][ks][1], u0b);
                uint32_t a02 = hmul2u(bse[0][ks][2], u0a);
                uint32_t a03 = hmul2u(bse[0][ks][3], u0b);
                uint32_t a10 = hmul2u(bse[1][ks][0], u1a);
                uint32_t a11 = hmul2u(bse[1][ks][1], u1b);
                uint32_t a12 = hmul2u(bse[1][ks][2], u1a);
                uint32_t a13 = hmul2u(bse[1][ks][3], u1b);
#pragma unroll
                for (int nt = 0; nt < NTILES; ++nt) {
                    uint32_t b0, b1;
                    asm volatile("ld.shared.v2.b32 {%0,%1}, [%2];"
                        : "=r"(b0), "=r"(b1)
                        : "r"(wb + nt * (8 * W_ROW_STRIDE) + ks * 32));
                    MMA16816(acc[0][nt], a00, a01, a02, a03, b0, b1);
                    MMA16816(acc[1][nt], a10, a11, a12, a13, b0, b1);
                }
            }
        }
    }

    // ---- epilogue: fused split-K reduction via red.global.add ----
#pragma unroll
    for (int mt = 0; mt < 2; ++mt) {
        const int r0 = R + 16 * mt + lq;
#pragma unroll
        for (int nt = 0; nt < NTILES; ++nt) {
            const int col = nt * 8 + lr * 2;
            if (col < NC) {
                redg_add(out + (size_t)r0 * NC + col,       acc[mt][nt][0]);
                redg_add(out + (size_t)(r0 + 8) * NC + col, acc[mt][nt][2]);
            }
            if (col + 1 < NC) {
                redg_add(out + (size_t)r0 * NC + col + 1,       acc[mt][nt][1]);
                redg_add(out + (size_t)(r0 + 8) * NC + col + 1, acc[mt][nt][3]);
            }
        }
    }
}

// ================= launch =================
extern "C" void kernel_launch(void* const* d_in, const int* in_sizes, int n_in,
                              void* d_out, int out_size) {
    const float* head = (const float*)d_in[0];
    const float* tail = (const float*)d_in[1];
    const float* W    = (const float*)d_in[2];
    const float* b    = (const float*)d_in[3];
    float* out        = (float*)d_out;

    cudaFuncSetAttribute(bilinear_mma,
                         cudaFuncAttributeMaxDynamicSharedMemorySize, SMEM_BYTES);

    // 1) W -> fp16, fragment-interleaved (L2-resident afterwards)
    convert_w<<<(NC * KTOT / 4 + 255) / 256, 256>>>((const float4*)W);
    // 2) out = bias broadcast (out is poisoned before timing)
    init_bias<<<(NROWS * NC + 255) / 256, 256>>>(b, out);
    // 3) fused bilinear GEMM, split-K accumulated into out via REDG
    dim3 grid(NROWS / M_PER_CTA, SPLITS);   // (16, 9) = 144 CTAs
    bilinear_mma<<<grid, THREADS, SMEM_BYTES>>>(head, tail, out);
}

// round 15
// speedup vs baseline: 1.0181x; 1.0085x over previous
#include <cuda_runtime.h>
#include <cuda_fp16.h>
#include <cstdint>

// ================= problem constants =================
#define NROWS 4096
#define EMB   768
#define NC    97
#define KTOT  49152          // 768 * 64
#define NTILES 13            // 13 x n8 = 104 >= 97
#define SPLITS 9             // 144 CTAs total (16 x 9)
#define THREADS 256
#define M_PER_CTA 256        // 8 warps x 32 rows

// W smem layout: per class row 160B stride; k16-step ks at byte ks*32,
// fragment pair lr at +lr*8 = [b0|b1]. ld.shared.v2.b32 conflict-free.
#define W_ROW_STRIDE 160
#define WSTAGE (104 * W_ROW_STRIDE)     // 16640 B per K64 chunk
#define QUAD   4                        // chunks per pipeline stage (K256)
#define SMEM_BYTES (2 * QUAD * WSTAGE)  // 2-slot ring = 133120 B

__device__ __align__(16) uint32_t g_Wh[NC * KTOT / 2];           // ~9.5 MB

__device__ __forceinline__ uint32_t f22h(float a, float b) {
    __half2 h = __floats2half2_rn(a, b);
    return *reinterpret_cast<uint32_t*>(&h);
}
__device__ __forceinline__ uint32_t hmul2u(uint32_t a, uint32_t s) {
    __half2 r = __hmul2(*reinterpret_cast<__half2*>(&a), *reinterpret_cast<__half2*>(&s));
    return *reinterpret_cast<uint32_t*>(&r);
}
__device__ __forceinline__ uint32_t smem_u32(const void* p) {
    uint32_t a;
    asm("{ .reg .u64 t; cvta.to.shared.u64 t, %1; cvt.u32.u64 %0, t; }" : "=r"(a) : "l"(p));
    return a;
}
__device__ __forceinline__ void cp16(uint32_t dst, const void* src) {
    asm volatile("cp.async.cg.shared.global [%0], [%1], 16;" :: "r"(dst), "l"(src));
}
#define CP_COMMIT()   asm volatile("cp.async.commit_group;" ::: "memory")
#define CP_WAIT_ALL() asm volatile("cp.async.wait_group 0;" ::: "memory")
__device__ __forceinline__ void redg_add(float* p, float v) {
    asm volatile("red.global.add.f32 [%0], %1;" :: "l"(p), "f"(v) : "memory");
}

// m16n8k16 fp16->fp32 mma, D==C in-place accumulate (baseline PTX, sm_80+)
#define MMA16816(d, a0, a1, a2, a3, b0, b1)                                      \
    asm volatile("mma.sync.aligned.m16n8k16.row.col.f32.f16.f16.f32 "            \
        "{%0,%1,%2,%3},{%4,%5,%6,%7},{%8,%9},{%0,%1,%2,%3};\n"                   \
        : "+f"((d)[0]), "+f"((d)[1]), "+f"((d)[2]), "+f"((d)[3])                 \
        : "r"(a0), "r"(a1), "r"(a2), "r"(a3), "r"(b0), "r"(b1))

// ================= kernels =================
// W fp32 -> fp16, remapped so each k16 fragment pair lies contiguous.
__global__ void convert_w(const float4* __restrict__ W4) {
    size_t idx = (size_t)blockIdx.x * 256 + threadIdx.x;
    if (idx >= (size_t)NC * KTOT / 4) return;
    size_t j4 = idx * 4;
    int    ce = (int)(j4 & 63);
    int    ks = ce >> 4, h = (ce >> 3) & 1, q = (ce >> 2) & 1;
    size_t base_u32 = (j4 - ce) >> 1;
    int    w0 = ks * 8 + q * 4 + h;
    float4 v = W4[idx];
    g_Wh[base_u32 + w0]     = f22h(v.x, v.y);
    g_Wh[base_u32 + w0 + 2] = f22h(v.z, v.w);
}

__global__ void init_bias(const float* __restrict__ b, float* __restrict__ out) {
    int idx = blockIdx.x * 256 + threadIdx.x;
    if (idx < NROWS * NC) out[idx] = b[idx % NC];
}

// stage a K256 quad (4 chunks) of W into the smem ring (async)
__device__ __forceinline__ void stage_quad(uint32_t dst, int chunk, int t) {
#pragma unroll
    for (int c2 = 0; c2 < QUAD; ++c2) {
        const char* src = (const char*)g_Wh + (size_t)(chunk + c2) * 128;
#pragma unroll
        for (int base = 0; base < NC * 8; base += THREADS) {
            int idx = base + t;
            if (idx < NC * 8) {
                int c = idx >> 3, g = idx & 7;
                cp16(dst + c2 * WSTAGE + c * W_ROW_STRIDE + g * 16,
                     src + (size_t)c * (KTOT * 2) + g * 16);
            }
        }
    }
    CP_COMMIT();
}

__global__ void __launch_bounds__(THREADS, 1) bilinear_mma(
    const float* __restrict__ head, const float* __restrict__ tail,
    float* __restrict__ out)
{
    extern __shared__ __align__(16) char ws[];
    const uint32_t ws_u32 = smem_u32(ws);

    const int t     = threadIdx.x;
    const int w     = t >> 5;
    const int lane  = t & 31;
    const int lq    = lane >> 2;
    const int lr    = lane & 3;
    const int mbase = blockIdx.x * M_PER_CTA;
    const int split = blockIdx.y;
    // 192 K256-quads over 9 splits: 3 splits of 22, 6 of 21
    const int quad0  = split * 21 + (split < 3 ? split : 3);
    const int nq     = 21 + (split < 3 ? 1 : 0);
    const int chunk0 = quad0 * QUAD;
    const int R      = mbase + 32 * w;

    // zero both ring slots once (pad classes 97..103 stay 0 forever)
    for (int i = t; i < SMEM_BYTES / 4; i += THREADS)
        reinterpret_cast<uint32_t*>(ws)[i] = 0;
    __syncthreads();

    // master accumulators: [mtile][ntile][4] = 32 rows x 104 cols per warp
    float acc[2][NTILES][4];
#pragma unroll
    for (int mt = 0; mt < 2; ++mt)
#pragma unroll
        for (int nt = 0; nt < NTILES; ++nt)
#pragma unroll
            for (int q = 0; q < 4; ++q) acc[mt][nt][q] = 0.0f;

    // unscaled fp16 b2 fragments, static per k-block: [mtile][kstep][4]
    uint32_t bse[2][4][4];
    int curk = -1;

    stage_quad(ws_u32, chunk0, t);

#pragma unroll 1
    for (int qi = 0; qi < nq; ++qi) {
        const int chunk = chunk0 + QUAD * qi;
        const int kblk  = chunk >> 6;        // constant across the quad
        const int slot  = qi & 1;

        CP_WAIT_ALL();
        __syncthreads();   // quad(qi) ready; other ring slot consumers done

        if (qi + 1 < nq)
            stage_quad(ws_u32 + (1 - slot) * QUAD * WSTAGE, chunk + QUAD, t);

        // ---- refill b2 base fragments on k-block change ----
        if (kblk != curk) {
            curk = kblk;
#pragma unroll
            for (int mt = 0; mt < 2; ++mt) {
                const float* p0 = tail + (size_t)(R + 16 * mt + lq) * EMB + kblk * 64 + lr * 2;
                const float* p1 = p0 + 8 * EMB;
#pragma unroll
                for (int ks = 0; ks < 4; ++ks) {
                    float2 v0 = *reinterpret_cast<const float2*>(p0 + ks * 16);
                    float2 v1 = *reinterpret_cast<const float2*>(p1 + ks * 16);
                    float2 v2 = *reinterpret_cast<const float2*>(p0 + ks * 16 + 8);
                    float2 v3 = *reinterpret_cast<const float2*>(p1 + ks * 16 + 8);
                    bse[mt][ks][0] = f22h(v0.x, v0.y);
                    bse[mt][ks][1] = f22h(v1.x, v1.y);
                    bse[mt][ks][2] = f22h(v2.x, v2.y);
                    bse[mt][ks][3] = f22h(v3.x, v3.y);
                }
            }
        }

        // ---- batch-prefetch b1 scalars for all 4 sub-chunks (1 LDG.128/row) ----
        const size_t hcol0 = (size_t)kblk * 64 + (chunk & 63);
        float4 f0a = *reinterpret_cast<const float4*>(head + (size_t)(R +  0 + lq) * EMB + hcol0);
        float4 f0b = *reinterpret_cast<const float4*>(head + (size_t)(R +  8 + lq) * EMB + hcol0);
        float4 f1a = *reinterpret_cast<const float4*>(head + (size_t)(R + 16 + lq) * EMB + hcol0);
        float4 f1b = *reinterpret_cast<const float4*>(head + (size_t)(R + 24 + lq) * EMB + hcol0);
        const float s0a[4] = {f0a.x, f0a.y, f0a.z, f0a.w};
        const float s0b[4] = {f0b.x, f0b.y, f0b.z, f0b.w};
        const float s1a[4] = {f1a.x, f1a.y, f1a.z, f1a.w};
        const float s1b[4] = {f1b.x, f1b.y, f1b.z, f1b.w};

#pragma unroll
        for (int sub = 0; sub < QUAD; ++sub) {
            __half2 h0a = __float2half2_rn(s0a[sub]);
            __half2 h0b = __float2half2_rn(s0b[sub]);
            __half2 h1a = __float2half2_rn(s1a[sub]);
            __half2 h1b = __float2half2_rn(s1b[sub]);
            const uint32_t u0a = *reinterpret_cast<uint32_t*>(&h0a);
            const uint32_t u0b = *reinterpret_cast<uint32_t*>(&h0b);
            const uint32_t u1a = *reinterpret_cast<uint32_t*>(&h1a);
            const uint32_t u1b = *reinterpret_cast<uint32_t*>(&h1b);

            const uint32_t wb = ws_u32 + (slot * QUAD + sub) * WSTAGE
                              + lq * W_ROW_STRIDE + lr * 8;

            // ks-outer / nt-inner: dependent MMAs 26 apart -> pipe-rate bound
#pragma unroll
            for (int ks = 0; ks < 4; ++ks) {
                uint32_t a00 = hmul2u(bse[0][ks][0], u0a);
                uint32_t a01 = hmul2u(bse[0][ks][1], u0b);
                uint32_t a02 = hmul2u(bse[0][ks][2], u0a);
                uint32_t a03 = hmul2u(bse[0][ks][3], u0b);
                uint32_t a10 = hmul2u(bse[1][ks][0], u1a);
                uint32_t a11 = hmul2u(bse[1][ks][1], u1b);
                uint32_t a12 = hmul2u(bse[1][ks][2], u1a);
                uint32_t a13 = hmul2u(bse[1][ks][3], u1b);
#pragma unroll
                for (int nt = 0; nt < NTILES; ++nt) {
                    uint32_t b0, b1;
                    asm volatile("ld.shared.v2.b32 {%0,%1}, [%2];"
                        : "=r"(b0), "=r"(b1)
                        : "r"(wb + nt * (8 * W_ROW_STRIDE) + ks * 32));
                    MMA16816(acc[0][nt], a00, a01, a02, a03, b0, b1);
                    MMA16816(acc[1][nt], a10, a11, a12, a13, b0, b1);
                }
            }
        }
    }

    // ---- epilogue: fused split-K reduction via red.global.add ----
#pragma unroll
    for (int mt = 0; mt < 2; ++mt) {
        const int r0 = R + 16 * mt + lq;
#pragma unroll
        for (int nt = 0; nt < NTILES; ++nt) {
            const int col = nt * 8 + lr * 2;
            if (col < NC) {
                redg_add(out + (size_t)r0 * NC + col,       acc[mt][nt][0]);
                redg_add(out + (size_t)(r0 + 8) * NC + col, acc[mt][nt][2]);
            }
            if (col + 1 < NC) {
                redg_add(out + (size_t)r0 * NC + col + 1,       acc[mt][nt][1]);
                redg_add(out + (size_t)(r0 + 8) * NC + col + 1, acc[mt][nt][3]);
            }
        }
    }
}

// ================= launch =================
extern "C" void kernel_launch(void* const* d_in, const int* in_sizes, int n_in,
                              void* d_out, int out_size) {
    const float* head = (const float*)d_in[0];
    const float* tail = (const float*)d_in[1];
    const float* W    = (const float*)d_in[2];
    const float* b    = (const float*)d_in[3];
    float* out        = (float*)d_out;

    cudaFuncSetAttribute(bilinear_mma,
                         cudaFuncAttributeMaxDynamicSharedMemorySize, SMEM_BYTES);

    // 1) W -> fp16, fragment-interleaved (L2-resident afterwards)
    convert_w<<<(NC * KTOT / 4 + 255) / 256, 256>>>((const float4*)W);
    // 2) out = bias broadcast (out is poisoned before timing)
    init_bias<<<(NROWS * NC + 255) / 256, 256>>>(b, out);
    // 3) fused bilinear GEMM, split-K accumulated into out via REDG
    dim3 grid(NROWS / M_PER_CTA, SPLITS);   // (16, 9) = 144 CTAs
    bilinear_mma<<<grid, THREADS, SMEM_BYTES>>>(head, tail, out);
}